// round 16
// baseline (speedup 1.0000x reference)
#include <cuda_runtime.h>
#include <cuda_bf16.h>
#include <cuda_fp16.h>
#include <cstdint>

// ---------------- geometry ----------------
constexpr int B = 8;
constexpr int D0=50,H0=60,W0=65;
constexpr int D1=47,H1=57,W1=62;
constexpr int D2=44,H2=54,W2=59;
constexpr int DP1=40,HP1=50,WP1=55;
constexpr int D3=37,H3=47,W3=52;
constexpr int D4=34,H4=44,W4=49;
constexpr int DP2=30,HP2=40,WP2=45;
constexpr int D5=27,H5=37,W5=42;
constexpr int D6=24,H6=34,W6=39;
constexpr int D7=21,H7=31,W7=36;
constexpr int DP3=17,HP3=27,WP3=32;

constexpr long long SP0=(long long)D0*H0*W0;
constexpr long long SP1=(long long)D1*H1*W1;
constexpr long long SP2=(long long)D2*H2*W2;
constexpr long long SPP1=(long long)DP1*HP1*WP1;
constexpr long long SP3=(long long)D3*H3*W3;
constexpr long long SP4=(long long)D4*H4*W4;
constexpr long long SPP2=(long long)DP2*HP2*WP2;
constexpr long long SP5=(long long)D5*H5*W5;
constexpr long long SP6=(long long)D6*H6*W6;
constexpr long long SP7=(long long)D7*H7*W7;
constexpr long long SPP3=(long long)DP3*HP3*WP3;   // 14688

// ---------------- scratch heap ----------------
constexpr size_t OFF_DENSE = 0;
constexpr size_t OFF_MASK0 = OFF_DENSE + B*SP0;
constexpr size_t OFF_X1    = OFF_MASK0 + B*SP0;
constexpr size_t OFF_M1    = OFF_X1  + (size_t)B*32*SP1;
constexpr size_t OFF_X2    = OFF_M1  + B*SP1;
constexpr size_t OFF_M2    = OFF_X2  + (size_t)B*32*SP2;
constexpr size_t OFF_P1    = OFF_M2  + B*SP2;
constexpr size_t OFF_MP1   = OFF_P1  + (size_t)B*32*SPP1;
constexpr size_t OFF_X3    = OFF_MP1 + B*SPP1;
constexpr size_t OFF_M3    = OFF_X3  + (size_t)B*32*SP3;
constexpr size_t OFF_X4    = OFF_M3  + B*SP3;
constexpr size_t OFF_M4    = OFF_X4  + (size_t)B*32*SP4;
constexpr size_t OFF_P2    = OFF_M4  + B*SP4;
constexpr size_t OFF_MP2   = OFF_P2  + (size_t)B*32*SPP2;
constexpr size_t OFF_X5    = OFF_MP2 + B*SPP2;
constexpr size_t OFF_M5    = OFF_X5  + (size_t)B*32*SP5;
constexpr size_t OFF_X6    = OFF_M5  + B*SP5;
constexpr size_t OFF_M6    = OFF_X6  + (size_t)B*32*SP6;
constexpr size_t OFF_X7    = OFF_M6  + B*SP6;
constexpr size_t OFF_M7    = OFF_X7  + B*SP7;
constexpr size_t OFF_P3    = OFF_M7  + B*SP7;
constexpr size_t OFF_MP3   = OFF_P3  + B*SPP3;
constexpr size_t OFF_WF    = OFF_MP3 + B*SPP3;
constexpr size_t OFF_H1    = OFF_WF  + 131072;
constexpr size_t OFF_H2    = OFF_H1  + 8000;
constexpr size_t OFF_PART  = OFF_H2  + 8000;
constexpr size_t OFF_SCRA  = OFF_PART+ 256000;
constexpr size_t OFF_SCRB  = OFF_SCRA+ 33500000;
constexpr size_t OFF_MSA   = OFF_SCRB+ 33500000;
constexpr size_t OFF_MSB   = OFF_MSA + 1700000;
constexpr size_t OFF_XHL   = OFF_MSB + 1700000;
constexpr size_t HEAP_TOTAL= OFF_XHL + 85100000;

__device__ float g_heap[HEAP_TOTAL];
__device__ int   g_win[B*SP0];

__device__ __forceinline__ float lrelu(float x){ return x >= 0.f ? x : 0.01f*x; }
__device__ __forceinline__ void ffma2(unsigned long long &d, unsigned long long a,
                                      unsigned long long b){
    asm("fma.rn.f32x2 %0, %1, %2, %0;" : "+l"(d) : "l"(a), "l"(b));
}
__device__ __forceinline__ unsigned long long dup2(float x){
    unsigned long long r;
    asm("mov.b64 %0, {%1, %1};" : "=l"(r) : "r"(__float_as_uint(x)));
    return r;
}
__device__ __forceinline__ unsigned long long pack2(float a, float b){
    unsigned long long r;
    asm("mov.b64 %0, {%1, %2};" : "=l"(r) : "r"(__float_as_uint(a)), "r"(__float_as_uint(b)));
    return r;
}
__device__ __forceinline__ void mma_f16(float c[4],
        unsigned a0, unsigned a1, unsigned a2, unsigned a3,
        unsigned b0, unsigned b1){
    asm("mma.sync.aligned.m16n8k16.row.col.f32.f16.f16.f32 "
        "{%0,%1,%2,%3}, {%4,%5,%6,%7}, {%8,%9}, {%0,%1,%2,%3};"
        : "+f"(c[0]), "+f"(c[1]), "+f"(c[2]), "+f"(c[3])
        : "r"(a0), "r"(a1), "r"(a2), "r"(a3), "r"(b0), "r"(b1));
}
__device__ __forceinline__ unsigned pack_h2(float a, float b){
    __half2 h = __halves2half2(__float2half_rn(a), __float2half_rn(b));
    return *reinterpret_cast<unsigned*>(&h);
}
__device__ __forceinline__ uint2 pack_hilo(float a, float b){
    float ha = __half2float(__float2half_rn(a));
    float hb = __half2float(__float2half_rn(b));
    uint2 o;
    o.x = pack_h2(a, b);
    o.y = pack_h2(a - ha, b - hb);
    return o;
}

// ---------------- scatter (deterministic last-wins) ----------------
__global__ void k_zero(float* dense, float* mask, int* winner, long long n){
    long long i = blockIdx.x*256LL + threadIdx.x;
    if(i < n){ dense[i]=0.f; mask[i]=0.f; winner[i]=-1; }
}
__global__ void k_scatter_max(const int* __restrict__ coors, int* __restrict__ winner, int n){
    int i = blockIdx.x*256 + threadIdx.x;
    if(i >= n) return;
    int b=coors[4*i], z=coors[4*i+1], y=coors[4*i+2], x=coors[4*i+3];
    atomicMax(&winner[((long long)(b*D0+z)*H0+y)*W0+x], i);
}
__global__ void k_scatter_write(const float* __restrict__ feat, const int* __restrict__ coors,
                                const int* __restrict__ winner,
                                float* __restrict__ dense, float* __restrict__ mask, int n){
    int i = blockIdx.x*256 + threadIdx.x;
    if(i >= n) return;
    int b=coors[4*i], z=coors[4*i+1], y=coors[4*i+2], x=coors[4*i+3];
    long long cell = ((long long)(b*D0+z)*H0+y)*W0+x;
    if(winner[cell]==i){ dense[cell]=feat[i]; mask[cell]=1.f; }
}

// ---------------- conv1: 1->32, writes PACKED hi/lo output ----------------
__global__ void k_conv1(const float* __restrict__ dense, const float* __restrict__ mask,
                        const float* __restrict__ w, const float* __restrict__ bias,
                        uint2* __restrict__ pk, float* __restrict__ mout){
    __shared__ __align__(16) float sw[2048];
    __shared__ float sb[32];
    int tid = threadIdx.x;
    for(int i=tid;i<2048;i+=256){ int oc=i>>6, tap=i&63; sw[tap*32+oc]=w[i]; }
    if(tid<32) sb[tid]=bias[tid];
    __syncthreads();
    long long idx = blockIdx.x*256LL + tid;
    if(idx >= B*SP1) return;
    int ow = idx % W1; long long t = idx / W1;
    int oh = (int)(t % H1); t /= H1;
    int od = (int)(t % D1); int b = (int)(t / D1);
    unsigned long long acc[16];
    #pragma unroll
    for(int p=0;p<16;p++) acc[p]=0ull;
    float mw=0.f;
    const float* db = dense + (long long)b*SP0;
    const float* mb = mask  + (long long)b*SP0;
    #pragma unroll 1
    for(int kd=0;kd<4;kd++){
        #pragma unroll 1
        for(int kh=0;kh<4;kh++){
            long long ro = ((long long)(od+kd)*H0 + (oh+kh))*W0 + ow;
            const float* xr = db + ro;
            const float* mr = mb + ro;
            #pragma unroll
            for(int kw=0;kw<4;kw++){
                float x = xr[kw];
                mw = fmaxf(mw, mr[kw]);
                unsigned long long xd = dup2(x);
                const unsigned long long* wp =
                    (const unsigned long long*)(sw + (kd*16+kh*4+kw)*32);
                #pragma unroll
                for(int p=0;p<16;p++) ffma2(acc[p], wp[p], xd);
            }
        }
    }
    long long sp = ((long long)od*H1 + oh)*W1 + ow;
    bool on = mw > 0.f;
    mout[(long long)b*SP1 + sp] = on ? 1.f : 0.f;
    uint2* ob = pk + (long long)b*16*SP1 + sp;
    #pragma unroll
    for(int p=0;p<16;p++){
        float lo = __uint_as_float((unsigned)(acc[p] & 0xffffffffull));
        float hi = __uint_as_float((unsigned)(acc[p] >> 32));
        float v0 = on ? lrelu(lo + sb[2*p  ]) : 0.f;
        float v1 = on ? lrelu(hi + sb[2*p+1]) : 0.f;
        ob[(long long)p*SP1] = pack_hilo(v0, v1);
    }
}

// ---------------- weight fragment prep ----------------
__global__ void k_wprep(const float* __restrict__ w, uint4* __restrict__ wf){
    int tid = blockIdx.x*256 + threadIdx.x;
    if(tid >= 16384) return;
    int lane = tid & 31;
    int f = tid >> 5;
    int nt  = f & 3;
    int icg = (f>>2) & 1;
    int kw  = (f>>3) & 3;
    int s   = f>>5;
    int kd = s>>2, kh = s&3;
    int gq = lane>>2, lq = lane&3;
    int oc = nt*8 + gq;
    int tap = kd*16 + kh*4 + kw;
    float wv[4];
    #pragma unroll
    for(int j=0;j<4;j++){
        int k = (j<2) ? (2*lq + j) : (2*lq + 8 + (j-2));
        int ic = icg*16 + k;
        wv[j] = w[(long long)(oc*32+ic)*64 + tap];
    }
    float hv[4];
    #pragma unroll
    for(int j=0;j<4;j++) hv[j] = __half2float(__float2half_rn(wv[j]));
    uint4 o;
    o.x = pack_h2(wv[0], wv[1]);
    o.y = pack_h2(wv[2], wv[3]);
    o.z = pack_h2(wv[0]-hv[0], wv[1]-hv[1]);
    o.w = pack_h2(wv[2]-hv[2], wv[3]-hv[3]);
    wf[tid] = o;
}

// ---------------- conv 32->32 fp16 mma, 512 threads (16 warps), M=16/warp ----------------
__global__ __launch_bounds__(512)
void k_conv_mma(const uint2* __restrict__ xhl, const float* __restrict__ m2,
                const uint4* __restrict__ wf, const float* __restrict__ bias,
                float* __restrict__ xf, uint2* __restrict__ pk,
                int Di,int Hi,int Wi,int Do,int Ho,int Wo){
    __shared__ __align__(16) uint4 swq[2048];   // double-buffered weight stage
    __shared__ float sbias[32];
    int tid = threadIdx.x, lane = tid & 31, warp = tid >> 5;
    int b = blockIdx.z, od = blockIdx.y;
    int HoWo = Ho*Wo;
    int gq = lane>>2, lq = lane&3;
    int v0 = blockIdx.x*256 + warp*16 + gq;
    int v1 = v0 + 8;
    int v0c = v0 < HoWo ? v0 : HoWo-1;
    int v1c = v1 < HoWo ? v1 : HoWo-1;
    int sp0 = (v0c/Wo)*Wi + (v0c%Wo);
    int sp1 = (v1c/Wo)*Wi + (v1c%Wo);
    long long inSp = (long long)Di*Hi*Wi;
    const uint2* xpA = xhl + ((long long)(b*16) + lq    )*inSp;
    const uint2* xpB = xhl + ((long long)(b*16) + lq + 4)*inSp;
    if(tid < 32) sbias[tid] = bias[tid];

    unsigned sbase = (unsigned)__cvta_generic_to_shared(swq);
    auto stage = [&](int s, int buf){
        const uint4* src = wf + s*1024 + tid;
        unsigned d = sbase + (unsigned)((buf*1024 + tid)*16);
        #pragma unroll
        for(int i=0;i<2;i++){
            asm volatile("cp.async.cg.shared.global [%0], [%1], 16;"
                :: "r"(d + i*512*16), "l"(src + i*512));
        }
        asm volatile("cp.async.commit_group;" ::: "memory");
    };

    float c[4][4];
    #pragma unroll
    for(int n=0;n<4;n++){
        #pragma unroll
        for(int j=0;j<4;j++) c[n][j]=0.f;
    }

    stage(0,0);
    #pragma unroll 1
    for(int s=0; s<16; s++){
        if(s<15){
            stage(s+1, (s+1)&1);
            asm volatile("cp.async.wait_group 1;" ::: "memory");
        }else{
            asm volatile("cp.async.wait_group 0;" ::: "memory");
        }
        __syncthreads();
        int kd = s>>2, kh = s&3;
        const uint4* wbase = swq + (s&1)*1024;
        long long sOff = (long long)(od+kd)*Hi*Wi + kh*Wi;
        #pragma unroll 1
        for(int icg=0;icg<2;icg++){
            long long po = sOff + (long long)(icg*8)*inSp;
            const uint2* pA = xpA + po;
            const uint2* pB = xpB + po;
            uint2 A0[4], A1[4], A2[4], A3[4];
            #pragma unroll
            for(int kw=0;kw<4;kw++){
                A0[kw] = pA[sp0+kw];
                A1[kw] = pA[sp1+kw];
                A2[kw] = pB[sp0+kw];
                A3[kw] = pB[sp1+kw];
            }
            #pragma unroll
            for(int kw=0;kw<4;kw++){
                const uint4* bf = wbase + ((kw*2+icg)*4)*32 + lane;
                #pragma unroll
                for(int n=0;n<4;n++){
                    uint4 bv = bf[n*32];
                    mma_f16(c[n], A0[kw].x,A1[kw].x,A2[kw].x,A3[kw].x, bv.x, bv.y); // hh
                    mma_f16(c[n], A0[kw].x,A1[kw].x,A2[kw].x,A3[kw].x, bv.z, bv.w); // hl
                    mma_f16(c[n], A0[kw].y,A1[kw].y,A2[kw].y,A3[kw].y, bv.x, bv.y); // lh
                }
            }
        }
        __syncthreads();
    }

    const float* mrow = m2 + ((long long)b*Do + od)*HoWo;
    long long outSp = (long long)Do*HoWo;
    bool on0 = (v0 < HoWo) && (mrow[v0c] > 0.f);
    bool on1 = (v1 < HoWo) && (mrow[v1c] > 0.f);
    #pragma unroll
    for(int n=0;n<4;n++){
        int oc0 = n*8 + lq*2;
        float bb0 = sbias[oc0], bb1 = sbias[oc0+1];
        float y00 = on0 ? lrelu(c[n][0] + bb0) : 0.f;
        float y01 = on0 ? lrelu(c[n][1] + bb1) : 0.f;
        float y10 = on1 ? lrelu(c[n][2] + bb0) : 0.f;
        float y11 = on1 ? lrelu(c[n][3] + bb1) : 0.f;
        if(xf){
            long long o0 = ((long long)(b*32) + oc0)*outSp + (long long)od*HoWo;
            long long o1 = o0 + outSp;
            if(v0 < HoWo){ xf[o0 + v0] = y00; xf[o1 + v0] = y01; }
            if(v1 < HoWo){ xf[o0 + v1] = y10; xf[o1 + v1] = y11; }
        }
        if(pk){
            int pair = n*4 + lq;
            uint2* o = pk + ((long long)(b*16) + pair)*outSp + (long long)od*HoWo;
            if(v0 < HoWo) o[v0] = pack_hilo(y00, y01);
            if(v1 < HoWo) o[v1] = pack_hilo(y10, y11);
        }
    }
}

// ---------------- conv7: 32->1 (f32x2) ----------------
__global__ void k_conv7(const float* __restrict__ xin, const float* __restrict__ min_,
                        const float* __restrict__ w, const float* __restrict__ bias,
                        float* __restrict__ xout, float* __restrict__ mout){
    __shared__ float sw[2048];
    int tid = threadIdx.x;
    for(int i=tid;i<2048;i+=256) sw[i]=w[i];
    __syncthreads();
    long long idx = blockIdx.x*256LL + tid;
    if(idx >= B*SP7) return;
    int ow = (int)(idx % W7); long long t = idx / W7;
    int oh = (int)(t % H7); t /= H7;
    int od = (int)(t % D7); int b = (int)(t / D7);
    const float* xb = xin + (long long)b*32*SP6;
    unsigned long long acc2 = 0ull;
    #pragma unroll 1
    for(int ic=0;ic<32;ic++){
        const float* xc = xb + (long long)ic*SP6;
        #pragma unroll
        for(int kd=0;kd<4;kd++){
            #pragma unroll
            for(int kh=0;kh<4;kh++){
                const float* xr = xc + ((long long)(od+kd)*H6 + (oh+kh))*W6 + ow;
                const float* wp = sw + ic*64 + kd*16 + kh*4;
                ffma2(acc2, pack2(xr[0],xr[1]), pack2(wp[0],wp[1]));
                ffma2(acc2, pack2(xr[2],xr[3]), pack2(wp[2],wp[3]));
            }
        }
    }
    float acc = __uint_as_float((unsigned)(acc2 & 0xffffffffull))
              + __uint_as_float((unsigned)(acc2 >> 32));
    float mw = 0.f;
    const float* mb = min_ + (long long)b*SP6;
    #pragma unroll
    for(int kd=0;kd<4;kd++)
        #pragma unroll
        for(int kh=0;kh<4;kh++){
            const float* mr = mb + ((long long)(od+kd)*H6 + (oh+kh))*W6 + ow;
            mw = fmaxf(mw, fmaxf(fmaxf(mr[0],mr[1]), fmaxf(mr[2],mr[3])));
        }
    bool on = mw > 0.f;
    long long sp = ((long long)od*H7 + oh)*W7 + ow;
    xout[(long long)b*SP7 + sp] = on ? lrelu(acc + bias[0]) : 0.f;
    mout[(long long)b*SP7 + sp] = on ? 1.f : 0.f;
}

// ---------------- fused masked W+H window-max (k=5, x gated by mask) ----------------
__global__ void k_pool_wh(const float* __restrict__ x, const float* __restrict__ m,
                          float* __restrict__ out, int C,int Di,int Hi,int Wi,
                          int Ho,int Wo){
    __shared__ float s1[3186];
    __shared__ float s2[2970];
    int tid = threadIdx.x;
    long long slice = blockIdx.x;
    int d = (int)(slice % Di); long long t = slice / Di;
    int c = (int)(t % C);      int b = (int)(t / C);
    const float* xp = x + (((long long)(b*C+c)*Di + d))*Hi*Wi;
    const float* mp = m + (((long long)b*Di + d))*Hi*Wi;
    float NI = __int_as_float(0xff800000);
    int nin = Hi*Wi;
    for(int i=tid;i<nin;i+=256){
        float vv = xp[i];
        s1[i] = (mp[i] > 0.f) ? vv : NI;
    }
    __syncthreads();
    int nw = Hi*Wo;
    for(int i=tid;i<nw;i+=256){
        int h = i / Wo, wo = i % Wo;
        const float* r = s1 + h*Wi + wo;
        s2[i] = fmaxf(fmaxf(fmaxf(r[0],r[1]), fmaxf(r[2],r[3])), r[4]);
    }
    __syncthreads();
    int nh = Ho*Wo;
    float* op = out + (((long long)(b*C+c)*Di + d))*Ho*Wo;
    for(int i=tid;i<nh;i+=256){
        int ho = i / Wo, wo = i % Wo;
        const float* r = s2 + ho*Wo + wo;
        op[i] = fmaxf(fmaxf(fmaxf(r[0],r[Wo]), fmaxf(r[2*Wo],r[3*Wo])), r[4*Wo]);
    }
}

// ---------------- fused W+H window-max, single channel, runtime KT ----------------
__global__ void k_wh_max(const float* __restrict__ x, float* __restrict__ out,
                         int Di,int Hi,int Wi,int Ho,int Wo,int KT){
    __shared__ float s1[3534];
    __shared__ float s2[3363];
    int tid = threadIdx.x;
    long long slice = blockIdx.x;
    int d = (int)(slice % Di); int b = (int)(slice / Di);
    const float* xp = x + ((long long)b*Di + d)*Hi*Wi;
    int nin = Hi*Wi;
    for(int i=tid;i<nin;i+=256) s1[i] = xp[i];
    __syncthreads();
    int nw = Hi*Wo;
    for(int i=tid;i<nw;i+=256){
        int h = i / Wo, wo = i % Wo;
        const float* r = s1 + h*Wi + wo;
        float v = r[0];
        for(int k=1;k<KT;k++) v = fmaxf(v, r[k]);
        s2[i] = v;
    }
    __syncthreads();
    int nh = Ho*Wo;
    float* op = out + ((long long)b*Di + d)*Ho*Wo;
    for(int i=tid;i<nh;i+=256){
        int ho = i / Wo, wo = i % Wo;
        const float* r = s2 + ho*Wo + wo;
        float v = r[0];
        for(int k=1;k<KT;k++) v = fmaxf(v, r[k*Wo]);
        op[i] = v;
    }
}

__global__ void k_max_axis(const float* __restrict__ in, float* __restrict__ out,
                           long long pre, int Li, int Lo, long long post, int KT){
    long long n = pre*Lo*post;
    long long idx = blockIdx.x*256LL + threadIdx.x;
    if(idx >= n) return;
    long long q = idx % post; long long t = idx / post;
    int l = (int)(t % Lo); long long p = t / Lo;
    const float* ip = in + ((long long)p*Li + l)*post + q;
    float r = ip[0];
    for(int k=1;k<KT;k++) r = fmaxf(r, ip[(long long)k*post]);
    out[idx] = r;
}
__global__ void k_pool_final(const float* __restrict__ p, const float* __restrict__ m2,
                             float* __restrict__ xo, int C, long long sp){
    long long n = (long long)B*C*sp;
    long long idx = blockIdx.x*256LL + threadIdx.x;
    if(idx >= n) return;
    long long s = idx % sp; int b = (int)((idx / sp) / C);
    xo[idx] = m2[(long long)b*sp + s] > 0.f ? p[idx] : 0.f;
}
__global__ void k_pool_final_pk(const float* __restrict__ p, const float* __restrict__ m2,
                                uint2* __restrict__ xo, long long sp){
    long long n = (long long)B*16*sp;
    long long idx = blockIdx.x*256LL + threadIdx.x;
    if(idx >= n) return;
    long long s = idx % sp; long long t = idx / sp;
    int pair = (int)(t & 15); int b = (int)(t >> 4);
    bool on = m2[(long long)b*sp + s] > 0.f;
    float x0 = on ? p[((long long)(b*32 + 2*pair  ))*sp + s] : 0.f;
    float x1 = on ? p[((long long)(b*32 + 2*pair+1))*sp + s] : 0.f;
    xo[idx] = pack_hilo(x0, x1);
}

// ---------------- FC layers (split-K, deterministic reduce) ----------------
__global__ void k_fc_part(const float* __restrict__ in, const float* __restrict__ Wm,
                          float* __restrict__ part, int K, int N, int KCH){
    int col = blockIdx.x*128 + threadIdx.x;
    int kc = blockIdx.y;
    if(col >= N) return;
    int r0 = (int)((long long)K*kc/KCH), r1 = (int)((long long)K*(kc+1)/KCH);
    float acc[8];
    #pragma unroll
    for(int b=0;b<8;b++) acc[b]=0.f;
    for(int r=r0;r<r1;r++){
        float wv = Wm[(long long)r*N + col];
        #pragma unroll
        for(int b=0;b<8;b++) acc[b] += in[(long long)b*K + r]*wv;
    }
    #pragma unroll
    for(int b=0;b<8;b++) part[(long long)(kc*8+b)*N + col] = acc[b];
}
__global__ void k_fc_red(const float* __restrict__ part, const float* __restrict__ bias,
                         float* __restrict__ out, int N, int KCH){
    int col = blockIdx.x*128 + threadIdx.x;
    int b = blockIdx.y;
    if(col >= N) return;
    float s = bias[col];
    for(int k=0;k<KCH;k++) s += part[(long long)(k*8+b)*N + col];
    out[(long long)b*N + col] = lrelu(s);
}
__global__ void k_fc3(const float* __restrict__ h, const float* __restrict__ W10,
                      const float* __restrict__ b10, float* __restrict__ out){
    __shared__ float red[256];
    int b = blockIdx.x, t = threadIdx.x;
    float s = 0.f;
    for(int r=t;r<1000;r+=256) s += h[(long long)b*1000 + r]*W10[r];
    red[t] = s; __syncthreads();
    for(int o=128;o;o>>=1){ if(t<o) red[t]+=red[t+o]; __syncthreads(); }
    if(t==0) out[b] = lrelu(red[0] + b10[0]);
}

// ---------------- launch ----------------
static inline unsigned gdiv(long long n){ return (unsigned)((n + 255) / 256); }

static void run_pool_pk(float* x, float* m, uint2* pkout, float* mout,
                        int Di,int Hi,int Wi, int Do,int Ho,int Wo,
                        float* A, float* Bs, float* mA, float* mB){
    k_pool_wh<<<(unsigned)((long long)B*32*Di),256>>>(x, m, A, 32, Di, Hi, Wi, Ho, Wo);
    k_max_axis<<<gdiv((long long)B*32*Do*Ho*Wo),256>>>(A, Bs, (long long)B*32, Di, Do, (long long)Ho*Wo, 5);
    k_wh_max<<<(unsigned)((long long)B*Di),256>>>(m, mA, Di, Hi, Wi, Ho, Wo, 5);
    k_max_axis<<<gdiv((long long)B*Do*Ho*Wo),256>>>(mA, mout, (long long)B, Di, Do, (long long)Ho*Wo, 5);
    k_pool_final_pk<<<gdiv((long long)B*16*Do*Ho*Wo),256>>>(Bs, mout, pkout, (long long)Do*Ho*Wo);
}
static void run_pool_f(float* x, float* m, float* xout, float* mout,
                       int C, int Di,int Hi,int Wi, int Do,int Ho,int Wo,
                       float* A, float* Bs, float* mA, float* mB){
    k_pool_wh<<<(unsigned)((long long)B*C*Di),256>>>(x, m, A, C, Di, Hi, Wi, Ho, Wo);
    k_max_axis<<<gdiv((long long)B*C*Do*Ho*Wo),256>>>(A, Bs, (long long)B*C, Di, Do, (long long)Ho*Wo, 5);
    k_wh_max<<<(unsigned)((long long)B*Di),256>>>(m, mA, Di, Hi, Wi, Ho, Wo, 5);
    k_max_axis<<<gdiv((long long)B*Do*Ho*Wo),256>>>(mA, mout, (long long)B, Di, Do, (long long)Ho*Wo, 5);
    k_pool_final<<<gdiv((long long)B*C*Do*Ho*Wo),256>>>(Bs, mout, xout, C, (long long)Do*Ho*Wo);
}

static void run_conv_mma(const uint2* xpk, const float* min_, const float* w,
                         const float* bias, float* xoutF, uint2* xoutPK, float* mout,
                         int Di,int Hi,int Wi,int Do,int Ho,int Wo,
                         float* WF, float* mA, float* mB){
    k_wh_max<<<(unsigned)((long long)B*Di),256>>>(min_, mA, Di, Hi, Wi, Ho, Wo, 4);
    k_max_axis<<<gdiv((long long)B*Do*Ho*Wo),256>>>(mA, mout, (long long)B, Di, Do, (long long)Ho*Wo, 4);
    k_wprep<<<64,256>>>(w, (uint4*)WF);
    int HoWo = Ho*Wo;
    k_conv_mma<<<dim3((HoWo+255)/256, Do, B), 512>>>(
        xpk, mout, (const uint4*)WF, bias, xoutF, xoutPK, Di,Hi,Wi,Do,Ho,Wo);
}

extern "C" void kernel_launch(void* const* d_in, const int* in_sizes, int n_in,
                              void* d_out, int out_size){
    float* H; int* WIN;
    cudaGetSymbolAddress((void**)&H, g_heap);
    cudaGetSymbolAddress((void**)&WIN, g_win);

    const float* feat  = (const float*)d_in[0];
    const int*   coors = (const int*)  d_in[1];
    int base = (in_sizes[2] == 1) ? 3 : 2;
    const float* w1 =(const float*)d_in[base+0];  const float* b1 =(const float*)d_in[base+1];
    const float* w2 =(const float*)d_in[base+2];  const float* b2 =(const float*)d_in[base+3];
    const float* w3 =(const float*)d_in[base+4];  const float* b3 =(const float*)d_in[base+5];
    const float* w4 =(const float*)d_in[base+6];  const float* b4 =(const float*)d_in[base+7];
    const float* w5 =(const float*)d_in[base+8];  const float* b5 =(const float*)d_in[base+9];
    const float* w6 =(const float*)d_in[base+10]; const float* b6 =(const float*)d_in[base+11];
    const float* w7 =(const float*)d_in[base+12]; const float* b7 =(const float*)d_in[base+13];
    const float* W8 =(const float*)d_in[base+14]; const float* b8 =(const float*)d_in[base+15];
    const float* W9 =(const float*)d_in[base+16]; const float* b9 =(const float*)d_in[base+17];
    const float* W10=(const float*)d_in[base+18]; const float* b10=(const float*)d_in[base+19];
    int n = in_sizes[0];
    float* out = (float*)d_out;

    float* DENSE=H+OFF_DENSE; float* MASK0=H+OFF_MASK0;
    float* M1=H+OFF_M1;
    float* X2=H+OFF_X2; float* M2=H+OFF_M2;
    float* MP1=H+OFF_MP1;
    float* M3=H+OFF_M3;
    float* X4=H+OFF_X4; float* M4=H+OFF_M4;
    float* MP2=H+OFF_MP2;
    float* M5=H+OFF_M5;
    float* X6=H+OFF_X6; float* M6=H+OFF_M6;
    float* X7=H+OFF_X7; float* M7=H+OFF_M7;
    float* P3=H+OFF_P3; float* MP3=H+OFF_MP3;
    float* WF=H+OFF_WF; float* H1b=H+OFF_H1; float* H2b=H+OFF_H2;
    float* PART=H+OFF_PART;
    float* SA=H+OFF_SCRA; float* SB=H+OFF_SCRB;
    float* MA=H+OFF_MSA;  float* MB=H+OFF_MSB;
    uint2* PKA=(uint2*)(H+OFF_XHL);
    uint2* PKB=(uint2*)(H+OFF_XHL+42600000);

    // scatter
    k_zero<<<gdiv(B*SP0),256>>>(DENSE, MASK0, WIN, B*SP0);
    k_scatter_max<<<(n+255)/256,256>>>(coors, WIN, n);
    k_scatter_write<<<(n+255)/256,256>>>(feat, coors, WIN, DENSE, MASK0, n);

    // conv1 -> packed PKA
    k_conv1<<<gdiv(B*SP1),256>>>(DENSE, MASK0, w1, b1, PKA, M1);

    // conv2: PKA -> float X2
    run_conv_mma(PKA, M1, w2, b2, X2, nullptr, M2, D1,H1,W1, D2,H2,W2, WF, MA, MB);
    // pool1 -> packed PKB
    run_pool_pk(X2, M2, PKB, MP1, D2,H2,W2, DP1,HP1,WP1, SA, SB, MA, MB);
    // conv3: PKB -> packed PKA
    run_conv_mma(PKB, MP1, w3, b3, nullptr, PKA, M3, DP1,HP1,WP1, D3,H3,W3, WF, MA, MB);
    // conv4: PKA -> float X4
    run_conv_mma(PKA, M3, w4, b4, X4, nullptr, M4, D3,H3,W3, D4,H4,W4, WF, MA, MB);
    // pool2 -> packed PKB
    run_pool_pk(X4, M4, PKB, MP2, D4,H4,W4, DP2,HP2,WP2, SA, SB, MA, MB);
    // conv5: PKB -> packed PKA
    run_conv_mma(PKB, MP2, w5, b5, nullptr, PKA, M5, DP2,HP2,WP2, D5,H5,W5, WF, MA, MB);
    // conv6: PKA -> float X6
    run_conv_mma(PKA, M5, w6, b6, X6, nullptr, M6, D5,H5,W5, D6,H6,W6, WF, MA, MB);
    // conv7
    k_conv7<<<gdiv(B*SP7),256>>>(X6, M6, w7, b7, X7, M7);
    // pool3
    run_pool_f(X7, M7, P3, MP3, 1, D7,H7,W7, DP3,HP3,WP3, SA, SB, MA, MB);

    // FC stack
    k_fc_part<<<dim3(8,32),128>>>(P3, W8, PART, (int)SPP3, 1000, 32);
    k_fc_red <<<dim3(8,8), 128>>>(PART, b8, H1b, 1000, 32);
    k_fc_part<<<dim3(8,8), 128>>>(H1b, W9, PART, 1000, 1000, 8);
    k_fc_red <<<dim3(8,8), 128>>>(PART, b9, H2b, 1000, 8);
    k_fc3<<<8,256>>>(H2b, W10, b10, out);
}

// round 17
// speedup vs baseline: 1.1739x; 1.1739x over previous
#include <cuda_runtime.h>
#include <cuda_bf16.h>
#include <cuda_fp16.h>
#include <cstdint>

// ---------------- geometry ----------------
constexpr int B = 8;
constexpr int D0=50,H0=60,W0=65;
constexpr int D1=47,H1=57,W1=62;
constexpr int D2=44,H2=54,W2=59;
constexpr int DP1=40,HP1=50,WP1=55;
constexpr int D3=37,H3=47,W3=52;
constexpr int D4=34,H4=44,W4=49;
constexpr int DP2=30,HP2=40,WP2=45;
constexpr int D5=27,H5=37,W5=42;
constexpr int D6=24,H6=34,W6=39;
constexpr int D7=21,H7=31,W7=36;
constexpr int DP3=17,HP3=27,WP3=32;

constexpr long long SP0=(long long)D0*H0*W0;
constexpr long long SP1=(long long)D1*H1*W1;
constexpr long long SP2=(long long)D2*H2*W2;
constexpr long long SPP1=(long long)DP1*HP1*WP1;
constexpr long long SP3=(long long)D3*H3*W3;
constexpr long long SP4=(long long)D4*H4*W4;
constexpr long long SPP2=(long long)DP2*HP2*WP2;
constexpr long long SP5=(long long)D5*H5*W5;
constexpr long long SP6=(long long)D6*H6*W6;
constexpr long long SP7=(long long)D7*H7*W7;
constexpr long long SPP3=(long long)DP3*HP3*WP3;   // 14688

// ---------------- scratch heap ----------------
constexpr size_t OFF_DENSE = 0;
constexpr size_t OFF_MASK0 = OFF_DENSE + B*SP0;
constexpr size_t OFF_X1    = OFF_MASK0 + B*SP0;
constexpr size_t OFF_M1    = OFF_X1  + (size_t)B*32*SP1;
constexpr size_t OFF_X2    = OFF_M1  + B*SP1;
constexpr size_t OFF_M2    = OFF_X2  + (size_t)B*32*SP2;
constexpr size_t OFF_P1    = OFF_M2  + B*SP2;
constexpr size_t OFF_MP1   = OFF_P1  + (size_t)B*32*SPP1;
constexpr size_t OFF_X3    = OFF_MP1 + B*SPP1;
constexpr size_t OFF_M3    = OFF_X3  + (size_t)B*32*SP3;
constexpr size_t OFF_X4    = OFF_M3  + B*SP3;
constexpr size_t OFF_M4    = OFF_X4  + (size_t)B*32*SP4;
constexpr size_t OFF_P2    = OFF_M4  + B*SP4;
constexpr size_t OFF_MP2   = OFF_P2  + (size_t)B*32*SPP2;
constexpr size_t OFF_X5    = OFF_MP2 + B*SPP2;
constexpr size_t OFF_M5    = OFF_X5  + (size_t)B*32*SP5;
constexpr size_t OFF_X6    = OFF_M5  + B*SP5;
constexpr size_t OFF_M6    = OFF_X6  + (size_t)B*32*SP6;
constexpr size_t OFF_X7    = OFF_M6  + B*SP6;
constexpr size_t OFF_M7    = OFF_X7  + B*SP7;
constexpr size_t OFF_P3    = OFF_M7  + B*SP7;
constexpr size_t OFF_MP3   = OFF_P3  + B*SPP3;
constexpr size_t OFF_WF    = OFF_MP3 + B*SPP3;
constexpr size_t OFF_H1    = OFF_WF  + 131072;
constexpr size_t OFF_H2    = OFF_H1  + 8000;
constexpr size_t OFF_PART  = OFF_H2  + 8000;
constexpr size_t OFF_SCRA  = OFF_PART+ 256000;
constexpr size_t OFF_SCRB  = OFF_SCRA+ 33500000;
constexpr size_t OFF_MSA   = OFF_SCRB+ 33500000;
constexpr size_t OFF_MSB   = OFF_MSA + 1700000;
constexpr size_t OFF_XHL   = OFF_MSB + 1700000;
constexpr size_t HEAP_TOTAL= OFF_XHL + 85100000;

__device__ float g_heap[HEAP_TOTAL];
__device__ int   g_win[B*SP0];

__device__ __forceinline__ float lrelu(float x){ return x >= 0.f ? x : 0.01f*x; }
__device__ __forceinline__ void ffma2(unsigned long long &d, unsigned long long a,
                                      unsigned long long b){
    asm("fma.rn.f32x2 %0, %1, %2, %0;" : "+l"(d) : "l"(a), "l"(b));
}
__device__ __forceinline__ unsigned long long dup2(float x){
    unsigned long long r;
    asm("mov.b64 %0, {%1, %1};" : "=l"(r) : "r"(__float_as_uint(x)));
    return r;
}
__device__ __forceinline__ unsigned long long pack2(float a, float b){
    unsigned long long r;
    asm("mov.b64 %0, {%1, %2};" : "=l"(r) : "r"(__float_as_uint(a)), "r"(__float_as_uint(b)));
    return r;
}
__device__ __forceinline__ void mma_f16(float c[4],
        unsigned a0, unsigned a1, unsigned a2, unsigned a3,
        unsigned b0, unsigned b1){
    asm("mma.sync.aligned.m16n8k16.row.col.f32.f16.f16.f32 "
        "{%0,%1,%2,%3}, {%4,%5,%6,%7}, {%8,%9}, {%0,%1,%2,%3};"
        : "+f"(c[0]), "+f"(c[1]), "+f"(c[2]), "+f"(c[3])
        : "r"(a0), "r"(a1), "r"(a2), "r"(a3), "r"(b0), "r"(b1));
}
__device__ __forceinline__ unsigned pack_h2(float a, float b){
    __half2 h = __halves2half2(__float2half_rn(a), __float2half_rn(b));
    return *reinterpret_cast<unsigned*>(&h);
}
__device__ __forceinline__ uint2 pack_hilo(float a, float b){
    float ha = __half2float(__float2half_rn(a));
    float hb = __half2float(__float2half_rn(b));
    uint2 o;
    o.x = pack_h2(a, b);
    o.y = pack_h2(a - ha, b - hb);
    return o;
}

// ---------------- scatter (deterministic last-wins) ----------------
__global__ void k_zero(float* dense, float* mask, int* winner, long long n){
    long long i = blockIdx.x*256LL + threadIdx.x;
    if(i < n){ dense[i]=0.f; mask[i]=0.f; winner[i]=-1; }
}
__global__ void k_scatter_max(const int* __restrict__ coors, int* __restrict__ winner, int n){
    int i = blockIdx.x*256 + threadIdx.x;
    if(i >= n) return;
    int b=coors[4*i], z=coors[4*i+1], y=coors[4*i+2], x=coors[4*i+3];
    atomicMax(&winner[((long long)(b*D0+z)*H0+y)*W0+x], i);
}
__global__ void k_scatter_write(const float* __restrict__ feat, const int* __restrict__ coors,
                                const int* __restrict__ winner,
                                float* __restrict__ dense, float* __restrict__ mask, int n){
    int i = blockIdx.x*256 + threadIdx.x;
    if(i >= n) return;
    int b=coors[4*i], z=coors[4*i+1], y=coors[4*i+2], x=coors[4*i+3];
    long long cell = ((long long)(b*D0+z)*H0+y)*W0+x;
    if(winner[cell]==i){ dense[cell]=feat[i]; mask[cell]=1.f; }
}

// ---------------- conv1: 1->32, writes PACKED hi/lo output ----------------
__global__ void k_conv1(const float* __restrict__ dense, const float* __restrict__ mask,
                        const float* __restrict__ w, const float* __restrict__ bias,
                        uint2* __restrict__ pk, float* __restrict__ mout){
    __shared__ __align__(16) float sw[2048];
    __shared__ float sb[32];
    int tid = threadIdx.x;
    for(int i=tid;i<2048;i+=256){ int oc=i>>6, tap=i&63; sw[tap*32+oc]=w[i]; }
    if(tid<32) sb[tid]=bias[tid];
    __syncthreads();
    long long idx = blockIdx.x*256LL + tid;
    if(idx >= B*SP1) return;
    int ow = idx % W1; long long t = idx / W1;
    int oh = (int)(t % H1); t /= H1;
    int od = (int)(t % D1); int b = (int)(t / D1);
    unsigned long long acc[16];
    #pragma unroll
    for(int p=0;p<16;p++) acc[p]=0ull;
    float mw=0.f;
    const float* db = dense + (long long)b*SP0;
    const float* mb = mask  + (long long)b*SP0;
    #pragma unroll 1
    for(int kd=0;kd<4;kd++){
        #pragma unroll 1
        for(int kh=0;kh<4;kh++){
            long long ro = ((long long)(od+kd)*H0 + (oh+kh))*W0 + ow;
            const float* xr = db + ro;
            const float* mr = mb + ro;
            #pragma unroll
            for(int kw=0;kw<4;kw++){
                float x = xr[kw];
                mw = fmaxf(mw, mr[kw]);
                unsigned long long xd = dup2(x);
                const unsigned long long* wp =
                    (const unsigned long long*)(sw + (kd*16+kh*4+kw)*32);
                #pragma unroll
                for(int p=0;p<16;p++) ffma2(acc[p], wp[p], xd);
            }
        }
    }
    long long sp = ((long long)od*H1 + oh)*W1 + ow;
    bool on = mw > 0.f;
    mout[(long long)b*SP1 + sp] = on ? 1.f : 0.f;
    uint2* ob = pk + (long long)b*16*SP1 + sp;
    #pragma unroll
    for(int p=0;p<16;p++){
        float lo = __uint_as_float((unsigned)(acc[p] & 0xffffffffull));
        float hi = __uint_as_float((unsigned)(acc[p] >> 32));
        float v0 = on ? lrelu(lo + sb[2*p  ]) : 0.f;
        float v1 = on ? lrelu(hi + sb[2*p+1]) : 0.f;
        ob[(long long)p*SP1] = pack_hilo(v0, v1);
    }
}

// ---------------- weight fragment prep ----------------
__global__ void k_wprep(const float* __restrict__ w, uint4* __restrict__ wf){
    int tid = blockIdx.x*256 + threadIdx.x;
    if(tid >= 16384) return;
    int lane = tid & 31;
    int f = tid >> 5;
    int nt  = f & 3;
    int icg = (f>>2) & 1;
    int kw  = (f>>3) & 3;
    int s   = f>>5;
    int kd = s>>2, kh = s&3;
    int gq = lane>>2, lq = lane&3;
    int oc = nt*8 + gq;
    int tap = kd*16 + kh*4 + kw;
    float wv[4];
    #pragma unroll
    for(int j=0;j<4;j++){
        int k = (j<2) ? (2*lq + j) : (2*lq + 8 + (j-2));
        int ic = icg*16 + k;
        wv[j] = w[(long long)(oc*32+ic)*64 + tap];
    }
    float hv[4];
    #pragma unroll
    for(int j=0;j<4;j++) hv[j] = __half2float(__float2half_rn(wv[j]));
    uint4 o;
    o.x = pack_h2(wv[0], wv[1]);
    o.y = pack_h2(wv[2], wv[3]);
    o.z = pack_h2(wv[0]-hv[0], wv[1]-hv[1]);
    o.w = pack_h2(wv[2]-hv[2], wv[3]-hv[3]);
    wf[tid] = o;
}

// ---------------- conv 32->32 fp16 mma (R13-proven: 256 thr, M=16/warp) ----------------
__global__ __launch_bounds__(256)
void k_conv_mma(const uint2* __restrict__ xhl, const float* __restrict__ m2,
                const uint4* __restrict__ wf, const float* __restrict__ bias,
                float* __restrict__ xf, uint2* __restrict__ pk,
                int Di,int Hi,int Wi,int Do,int Ho,int Wo){
    __shared__ __align__(16) uint4 swq[2048];   // double-buffered weight stage
    __shared__ float sbias[32];
    int tid = threadIdx.x, lane = tid & 31, warp = tid >> 5;
    int b = blockIdx.z, od = blockIdx.y;
    int HoWo = Ho*Wo;
    int gq = lane>>2, lq = lane&3;
    int v0 = blockIdx.x*128 + warp*16 + gq;
    int v1 = v0 + 8;
    int v0c = v0 < HoWo ? v0 : HoWo-1;
    int v1c = v1 < HoWo ? v1 : HoWo-1;
    int sp0 = (v0c/Wo)*Wi + (v0c%Wo);
    int sp1 = (v1c/Wo)*Wi + (v1c%Wo);
    long long inSp = (long long)Di*Hi*Wi;
    const uint2* xpA = xhl + ((long long)(b*16) + lq    )*inSp;
    const uint2* xpB = xhl + ((long long)(b*16) + lq + 4)*inSp;
    if(tid < 32) sbias[tid] = bias[tid];

    unsigned sbase = (unsigned)__cvta_generic_to_shared(swq);
    auto stage = [&](int s, int buf){
        const uint4* src = wf + s*1024 + tid;
        unsigned d = sbase + (unsigned)((buf*1024 + tid)*16);
        #pragma unroll
        for(int i=0;i<4;i++){
            asm volatile("cp.async.cg.shared.global [%0], [%1], 16;"
                :: "r"(d + i*256*16), "l"(src + i*256));
        }
        asm volatile("cp.async.commit_group;" ::: "memory");
    };

    float c[4][4];
    #pragma unroll
    for(int n=0;n<4;n++){
        #pragma unroll
        for(int j=0;j<4;j++) c[n][j]=0.f;
    }

    stage(0,0);
    #pragma unroll 1
    for(int s=0; s<16; s++){
        if(s<15){
            stage(s+1, (s+1)&1);
            asm volatile("cp.async.wait_group 1;" ::: "memory");
        }else{
            asm volatile("cp.async.wait_group 0;" ::: "memory");
        }
        __syncthreads();
        int kd = s>>2, kh = s&3;
        const uint4* wbase = swq + (s&1)*1024;
        long long sOff = (long long)(od+kd)*Hi*Wi + kh*Wi;
        #pragma unroll 1
        for(int icg=0;icg<2;icg++){
            long long po = sOff + (long long)(icg*8)*inSp;
            const uint2* pA = xpA + po;
            const uint2* pB = xpB + po;
            // batched A gather: 16 LDG.64 outstanding
            uint2 A0[4], A1[4], A2[4], A3[4];
            #pragma unroll
            for(int kw=0;kw<4;kw++){
                A0[kw] = pA[sp0+kw];
                A1[kw] = pA[sp1+kw];
                A2[kw] = pB[sp0+kw];
                A3[kw] = pB[sp1+kw];
            }
            #pragma unroll
            for(int kw=0;kw<4;kw++){
                const uint4* bf = wbase + ((kw*2+icg)*4)*32 + lane;
                #pragma unroll
                for(int n=0;n<4;n++){
                    uint4 bv = bf[n*32];
                    mma_f16(c[n], A0[kw].x,A1[kw].x,A2[kw].x,A3[kw].x, bv.x, bv.y); // hh
                    mma_f16(c[n], A0[kw].x,A1[kw].x,A2[kw].x,A3[kw].x, bv.z, bv.w); // hl
                    mma_f16(c[n], A0[kw].y,A1[kw].y,A2[kw].y,A3[kw].y, bv.x, bv.y); // lh
                }
            }
        }
        __syncthreads();
    }

    // epilogue: mask gate + bias + lrelu; write float and/or packed
    const float* mrow = m2 + ((long long)b*Do + od)*HoWo;
    long long outSp = (long long)Do*HoWo;
    bool on0 = (v0 < HoWo) && (mrow[v0c] > 0.f);
    bool on1 = (v1 < HoWo) && (mrow[v1c] > 0.f);
    #pragma unroll
    for(int n=0;n<4;n++){
        int oc0 = n*8 + lq*2;
        float bb0 = sbias[oc0], bb1 = sbias[oc0+1];
        float y00 = on0 ? lrelu(c[n][0] + bb0) : 0.f;
        float y01 = on0 ? lrelu(c[n][1] + bb1) : 0.f;
        float y10 = on1 ? lrelu(c[n][2] + bb0) : 0.f;
        float y11 = on1 ? lrelu(c[n][3] + bb1) : 0.f;
        if(xf){
            long long o0 = ((long long)(b*32) + oc0)*outSp + (long long)od*HoWo;
            long long o1 = o0 + outSp;
            if(v0 < HoWo){ xf[o0 + v0] = y00; xf[o1 + v0] = y01; }
            if(v1 < HoWo){ xf[o0 + v1] = y10; xf[o1 + v1] = y11; }
        }
        if(pk){
            int pair = n*4 + lq;
            uint2* o = pk + ((long long)(b*16) + pair)*outSp + (long long)od*HoWo;
            if(v0 < HoWo) o[v0] = pack_hilo(y00, y01);
            if(v1 < HoWo) o[v1] = pack_hilo(y10, y11);
        }
    }
}

// ---------------- conv7: 32->1 (f32x2) ----------------
__global__ void k_conv7(const float* __restrict__ xin, const float* __restrict__ min_,
                        const float* __restrict__ w, const float* __restrict__ bias,
                        float* __restrict__ xout, float* __restrict__ mout){
    __shared__ float sw[2048];
    int tid = threadIdx.x;
    for(int i=tid;i<2048;i+=256) sw[i]=w[i];
    __syncthreads();
    long long idx = blockIdx.x*256LL + tid;
    if(idx >= B*SP7) return;
    int ow = (int)(idx % W7); long long t = idx / W7;
    int oh = (int)(t % H7); t /= H7;
    int od = (int)(t % D7); int b = (int)(t / D7);
    const float* xb = xin + (long long)b*32*SP6;
    unsigned long long acc2 = 0ull;
    #pragma unroll 1
    for(int ic=0;ic<32;ic++){
        const float* xc = xb + (long long)ic*SP6;
        #pragma unroll
        for(int kd=0;kd<4;kd++){
            #pragma unroll
            for(int kh=0;kh<4;kh++){
                const float* xr = xc + ((long long)(od+kd)*H6 + (oh+kh))*W6 + ow;
                const float* wp = sw + ic*64 + kd*16 + kh*4;
                ffma2(acc2, pack2(xr[0],xr[1]), pack2(wp[0],wp[1]));
                ffma2(acc2, pack2(xr[2],xr[3]), pack2(wp[2],wp[3]));
            }
        }
    }
    float acc = __uint_as_float((unsigned)(acc2 & 0xffffffffull))
              + __uint_as_float((unsigned)(acc2 >> 32));
    float mw = 0.f;
    const float* mb = min_ + (long long)b*SP6;
    #pragma unroll
    for(int kd=0;kd<4;kd++)
        #pragma unroll
        for(int kh=0;kh<4;kh++){
            const float* mr = mb + ((long long)(od+kd)*H6 + (oh+kh))*W6 + ow;
            mw = fmaxf(mw, fmaxf(fmaxf(mr[0],mr[1]), fmaxf(mr[2],mr[3])));
        }
    bool on = mw > 0.f;
    long long sp = ((long long)od*H7 + oh)*W7 + ow;
    xout[(long long)b*SP7 + sp] = on ? lrelu(acc + bias[0]) : 0.f;
    mout[(long long)b*SP7 + sp] = on ? 1.f : 0.f;
}

// ---------------- fused masked W+H window-max (k=5, x gated by mask) ----------------
__global__ void k_pool_wh(const float* __restrict__ x, const float* __restrict__ m,
                          float* __restrict__ out, int C,int Di,int Hi,int Wi,
                          int Ho,int Wo){
    __shared__ float s1[3186];
    __shared__ float s2[2970];
    int tid = threadIdx.x;
    long long slice = blockIdx.x;
    int d = (int)(slice % Di); long long t = slice / Di;
    int c = (int)(t % C);      int b = (int)(t / C);
    const float* xp = x + (((long long)(b*C+c)*Di + d))*Hi*Wi;
    const float* mp = m + (((long long)b*Di + d))*Hi*Wi;
    float NI = __int_as_float(0xff800000);
    int nin = Hi*Wi;
    for(int i=tid;i<nin;i+=256){
        float vv = xp[i];
        s1[i] = (mp[i] > 0.f) ? vv : NI;
    }
    __syncthreads();
    int nw = Hi*Wo;
    for(int i=tid;i<nw;i+=256){
        int h = i / Wo, wo = i % Wo;
        const float* r = s1 + h*Wi + wo;
        s2[i] = fmaxf(fmaxf(fmaxf(r[0],r[1]), fmaxf(r[2],r[3])), r[4]);
    }
    __syncthreads();
    int nh = Ho*Wo;
    float* op = out + (((long long)(b*C+c)*Di + d))*Ho*Wo;
    for(int i=tid;i<nh;i+=256){
        int ho = i / Wo, wo = i % Wo;
        const float* r = s2 + ho*Wo + wo;
        op[i] = fmaxf(fmaxf(fmaxf(r[0],r[Wo]), fmaxf(r[2*Wo],r[3*Wo])), r[4*Wo]);
    }
}

// ---------------- fused W+H window-max, single channel, runtime KT ----------------
__global__ void k_wh_max(const float* __restrict__ x, float* __restrict__ out,
                         int Di,int Hi,int Wi,int Ho,int Wo,int KT){
    __shared__ float s1[3534];
    __shared__ float s2[3363];
    int tid = threadIdx.x;
    long long slice = blockIdx.x;
    int d = (int)(slice % Di); int b = (int)(slice / Di);
    const float* xp = x + ((long long)b*Di + d)*Hi*Wi;
    int nin = Hi*Wi;
    for(int i=tid;i<nin;i+=256) s1[i] = xp[i];
    __syncthreads();
    int nw = Hi*Wo;
    for(int i=tid;i<nw;i+=256){
        int h = i / Wo, wo = i % Wo;
        const float* r = s1 + h*Wi + wo;
        float v = r[0];
        for(int k=1;k<KT;k++) v = fmaxf(v, r[k]);
        s2[i] = v;
    }
    __syncthreads();
    int nh = Ho*Wo;
    float* op = out + ((long long)b*Di + d)*Ho*Wo;
    for(int i=tid;i<nh;i+=256){
        int ho = i / Wo, wo = i % Wo;
        const float* r = s2 + ho*Wo + wo;
        float v = r[0];
        for(int k=1;k<KT;k++) v = fmaxf(v, r[k*Wo]);
        op[i] = v;
    }
}

__global__ void k_max_axis(const float* __restrict__ in, float* __restrict__ out,
                           long long pre, int Li, int Lo, long long post, int KT){
    long long n = pre*Lo*post;
    long long idx = blockIdx.x*256LL + threadIdx.x;
    if(idx >= n) return;
    long long q = idx % post; long long t = idx / post;
    int l = (int)(t % Lo); long long p = t / Lo;
    const float* ip = in + ((long long)p*Li + l)*post + q;
    float r = ip[0];
    for(int k=1;k<KT;k++) r = fmaxf(r, ip[(long long)k*post]);
    out[idx] = r;
}
__global__ void k_pool_final(const float* __restrict__ p, const float* __restrict__ m2,
                             float* __restrict__ xo, int C, long long sp){
    long long n = (long long)B*C*sp;
    long long idx = blockIdx.x*256LL + threadIdx.x;
    if(idx >= n) return;
    long long s = idx % sp; int b = (int)((idx / sp) / C);
    xo[idx] = m2[(long long)b*sp + s] > 0.f ? p[idx] : 0.f;
}
__global__ void k_pool_final_pk(const float* __restrict__ p, const float* __restrict__ m2,
                                uint2* __restrict__ xo, long long sp){
    long long n = (long long)B*16*sp;
    long long idx = blockIdx.x*256LL + threadIdx.x;
    if(idx >= n) return;
    long long s = idx % sp; long long t = idx / sp;
    int pair = (int)(t & 15); int b = (int)(t >> 4);
    bool on = m2[(long long)b*sp + s] > 0.f;
    float x0 = on ? p[((long long)(b*32 + 2*pair  ))*sp + s] : 0.f;
    float x1 = on ? p[((long long)(b*32 + 2*pair+1))*sp + s] : 0.f;
    xo[idx] = pack_hilo(x0, x1);
}

// ---------------- FC layers (split-K, deterministic reduce) ----------------
__global__ void k_fc_part(const float* __restrict__ in, const float* __restrict__ Wm,
                          float* __restrict__ part, int K, int N, int KCH){
    int col = blockIdx.x*128 + threadIdx.x;
    int kc = blockIdx.y;
    if(col >= N) return;
    int r0 = (int)((long long)K*kc/KCH), r1 = (int)((long long)K*(kc+1)/KCH);
    float acc[8];
    #pragma unroll
    for(int b=0;b<8;b++) acc[b]=0.f;
    for(int r=r0;r<r1;r++){
        float wv = Wm[(long long)r*N + col];
        #pragma unroll
        for(int b=0;b<8;b++) acc[b] += in[(long long)b*K + r]*wv;
    }
    #pragma unroll
    for(int b=0;b<8;b++) part[(long long)(kc*8+b)*N + col] = acc[b];
}
__global__ void k_fc_red(const float* __restrict__ part, const float* __restrict__ bias,
                         float* __restrict__ out, int N, int KCH){
    int col = blockIdx.x*128 + threadIdx.x;
    int b = blockIdx.y;
    if(col >= N) return;
    float s = bias[col];
    for(int k=0;k<KCH;k++) s += part[(long long)(k*8+b)*N + col];
    out[(long long)b*N + col] = lrelu(s);
}
__global__ void k_fc3(const float* __restrict__ h, const float* __restrict__ W10,
                      const float* __restrict__ b10, float* __restrict__ out){
    __shared__ float red[256];
    int b = blockIdx.x, t = threadIdx.x;
    float s = 0.f;
    for(int r=t;r<1000;r+=256) s += h[(long long)b*1000 + r]*W10[r];
    red[t] = s; __syncthreads();
    for(int o=128;o;o>>=1){ if(t<o) red[t]+=red[t+o]; __syncthreads(); }
    if(t==0) out[b] = lrelu(red[0] + b10[0]);
}

// ---------------- launch ----------------
static inline unsigned gdiv(long long n){ return (unsigned)((n + 255) / 256); }

static void run_pool_pk(float* x, float* m, uint2* pkout, float* mout,
                        int Di,int Hi,int Wi, int Do,int Ho,int Wo,
                        float* A, float* Bs, float* mA, float* mB){
    k_pool_wh<<<(unsigned)((long long)B*32*Di),256>>>(x, m, A, 32, Di, Hi, Wi, Ho, Wo);
    k_max_axis<<<gdiv((long long)B*32*Do*Ho*Wo),256>>>(A, Bs, (long long)B*32, Di, Do, (long long)Ho*Wo, 5);
    k_wh_max<<<(unsigned)((long long)B*Di),256>>>(m, mA, Di, Hi, Wi, Ho, Wo, 5);
    k_max_axis<<<gdiv((long long)B*Do*Ho*Wo),256>>>(mA, mout, (long long)B, Di, Do, (long long)Ho*Wo, 5);
    k_pool_final_pk<<<gdiv((long long)B*16*Do*Ho*Wo),256>>>(Bs, mout, pkout, (long long)Do*Ho*Wo);
}
static void run_pool_f(float* x, float* m, float* xout, float* mout,
                       int C, int Di,int Hi,int Wi, int Do,int Ho,int Wo,
                       float* A, float* Bs, float* mA, float* mB){
    k_pool_wh<<<(unsigned)((long long)B*C*Di),256>>>(x, m, A, C, Di, Hi, Wi, Ho, Wo);
    k_max_axis<<<gdiv((long long)B*C*Do*Ho*Wo),256>>>(A, Bs, (long long)B*C, Di, Do, (long long)Ho*Wo, 5);
    k_wh_max<<<(unsigned)((long long)B*Di),256>>>(m, mA, Di, Hi, Wi, Ho, Wo, 5);
    k_max_axis<<<gdiv((long long)B*Do*Ho*Wo),256>>>(mA, mout, (long long)B, Di, Do, (long long)Ho*Wo, 5);
    k_pool_final<<<gdiv((long long)B*C*Do*Ho*Wo),256>>>(Bs, mout, xout, C, (long long)Do*Ho*Wo);
}

static void run_conv_mma(const uint2* xpk, const float* min_, const float* w,
                         const float* bias, float* xoutF, uint2* xoutPK, float* mout,
                         int Di,int Hi,int Wi,int Do,int Ho,int Wo,
                         float* WF, float* mA, float* mB){
    k_wh_max<<<(unsigned)((long long)B*Di),256>>>(min_, mA, Di, Hi, Wi, Ho, Wo, 4);
    k_max_axis<<<gdiv((long long)B*Do*Ho*Wo),256>>>(mA, mout, (long long)B, Di, Do, (long long)Ho*Wo, 4);
    k_wprep<<<64,256>>>(w, (uint4*)WF);
    int HoWo = Ho*Wo;
    k_conv_mma<<<dim3((HoWo+127)/128, Do, B), 256>>>(
        xpk, mout, (const uint4*)WF, bias, xoutF, xoutPK, Di,Hi,Wi,Do,Ho,Wo);
}

extern "C" void kernel_launch(void* const* d_in, const int* in_sizes, int n_in,
                              void* d_out, int out_size){
    float* H; int* WIN;
    cudaGetSymbolAddress((void**)&H, g_heap);
    cudaGetSymbolAddress((void**)&WIN, g_win);

    const float* feat  = (const float*)d_in[0];
    const int*   coors = (const int*)  d_in[1];
    int base = (in_sizes[2] == 1) ? 3 : 2;
    const float* w1 =(const float*)d_in[base+0];  const float* b1 =(const float*)d_in[base+1];
    const float* w2 =(const float*)d_in[base+2];  const float* b2 =(const float*)d_in[base+3];
    const float* w3 =(const float*)d_in[base+4];  const float* b3 =(const float*)d_in[base+5];
    const float* w4 =(const float*)d_in[base+6];  const float* b4 =(const float*)d_in[base+7];
    const float* w5 =(const float*)d_in[base+8];  const float* b5 =(const float*)d_in[base+9];
    const float* w6 =(const float*)d_in[base+10]; const float* b6 =(const float*)d_in[base+11];
    const float* w7 =(const float*)d_in[base+12]; const float* b7 =(const float*)d_in[base+13];
    const float* W8 =(const float*)d_in[base+14]; const float* b8 =(const float*)d_in[base+15];
    const float* W9 =(const float*)d_in[base+16]; const float* b9 =(const float*)d_in[base+17];
    const float* W10=(const float*)d_in[base+18]; const float* b10=(const float*)d_in[base+19];
    int n = in_sizes[0];
    float* out = (float*)d_out;

    float* DENSE=H+OFF_DENSE; float* MASK0=H+OFF_MASK0;
    float* M1=H+OFF_M1;
    float* X2=H+OFF_X2; float* M2=H+OFF_M2;
    float* MP1=H+OFF_MP1;
    float* M3=H+OFF_M3;
    float* X4=H+OFF_X4; float* M4=H+OFF_M4;
    float* MP2=H+OFF_MP2;
    float* M5=H+OFF_M5;
    float* X6=H+OFF_X6; float* M6=H+OFF_M6;
    float* X7=H+OFF_X7; float* M7=H+OFF_M7;
    float* P3=H+OFF_P3; float* MP3=H+OFF_MP3;
    float* WF=H+OFF_WF; float* H1b=H+OFF_H1; float* H2b=H+OFF_H2;
    float* PART=H+OFF_PART;
    float* SA=H+OFF_SCRA; float* SB=H+OFF_SCRB;
    float* MA=H+OFF_MSA;  float* MB=H+OFF_MSB;
    uint2* PKA=(uint2*)(H+OFF_XHL);
    uint2* PKB=(uint2*)(H+OFF_XHL+42600000);

    // scatter
    k_zero<<<gdiv(B*SP0),256>>>(DENSE, MASK0, WIN, B*SP0);
    k_scatter_max<<<(n+255)/256,256>>>(coors, WIN, n);
    k_scatter_write<<<(n+255)/256,256>>>(feat, coors, WIN, DENSE, MASK0, n);

    // conv1 -> packed PKA
    k_conv1<<<gdiv(B*SP1),256>>>(DENSE, MASK0, w1, b1, PKA, M1);

    // conv2: PKA -> float X2
    run_conv_mma(PKA, M1, w2, b2, X2, nullptr, M2, D1,H1,W1, D2,H2,W2, WF, MA, MB);
    // pool1 -> packed PKB
    run_pool_pk(X2, M2, PKB, MP1, D2,H2,W2, DP1,HP1,WP1, SA, SB, MA, MB);
    // conv3: PKB -> packed PKA
    run_conv_mma(PKB, MP1, w3, b3, nullptr, PKA, M3, DP1,HP1,WP1, D3,H3,W3, WF, MA, MB);
    // conv4: PKA -> float X4
    run_conv_mma(PKA, M3, w4, b4, X4, nullptr, M4, D3,H3,W3, D4,H4,W4, WF, MA, MB);
    // pool2 -> packed PKB
    run_pool_pk(X4, M4, PKB, MP2, D4,H4,W4, DP2,HP2,WP2, SA, SB, MA, MB);
    // conv5: PKB -> packed PKA
    run_conv_mma(PKB, MP2, w5, b5, nullptr, PKA, M5, DP2,HP2,WP2, D5,H5,W5, WF, MA, MB);
    // conv6: PKA -> float X6
    run_conv_mma(PKA, M5, w6, b6, X6, nullptr, M6, D5,H5,W5, D6,H6,W6, WF, MA, MB);
    // conv7
    k_conv7<<<gdiv(B*SP7),256>>>(X6, M6, w7, b7, X7, M7);
    // pool3
    run_pool_f(X7, M7, P3, MP3, 1, D7,H7,W7, DP3,HP3,WP3, SA, SB, MA, MB);

    // FC stack
    k_fc_part<<<dim3(8,32),128>>>(P3, W8, PART, (int)SPP3, 1000, 32);
    k_fc_red <<<dim3(8,8), 128>>>(PART, b8, H1b, 1000, 32);
    k_fc_part<<<dim3(8,8), 128>>>(H1b, W9, PART, 1000, 1000, 8);
    k_fc_red <<<dim3(8,8), 128>>>(PART, b9, H2b, 1000, 8);
    k_fc3<<<8,256>>>(H2b, W10, b10, out);
}